// round 2
// baseline (speedup 1.0000x reference)
#include <cuda_runtime.h>
#include <math.h>

#define T_TOK 2048
#define HIDDEN 5120
#define NH 32
#define DQ 128
#define DR 64
#define DV 128
#define QLORA 1536
#define KVLORA 512
#define KV_W (KVLORA + DR)        // 576
#define QDIM (DQ + DR)            // 192
#define KVUPW (NH * (DQ + DV))    // 8192
#define QW (NH * QDIM)            // 6144
#define ATTNW (NH * DV)           // 4096

// ---------------- scratch (device globals; no runtime allocation) ----------
__device__ float g_qa[T_TOK * QLORA];       // q_a then rmsnormed in place
__device__ float g_kv[T_TOK * KV_W];        // kv (first 512 rmsnormed in place)
__device__ float g_q[T_TOK * QW];           // q (pe part roped in place)
__device__ float g_kvup[T_TOK * KVUPW];     // k_nope | v per head
__device__ float g_kpe[T_TOK * DR];         // roped k_pe
__device__ float g_attn[T_TOK * ATTNW];     // attention output

// ---------------- generic SGEMM: C[M,N] = A[M,K] @ B[K,N] ------------------
// 128x128 block, BK=8, 256 threads, 8x8 register tile per thread.
// M must be a multiple of 128, K a multiple of 8, N a multiple of 4.
__global__ void sgemm_kernel(const float* __restrict__ A, int lda,
                             const float* __restrict__ B, int ldb,
                             float* __restrict__ C, int ldc,
                             int M, int N, int K) {
    __shared__ float As[8][128];
    __shared__ float Bs[8][128];
    const int tid = threadIdx.x;
    const int brow = blockIdx.y * 128;
    const int bcol = blockIdx.x * 128;
    const int tx = tid & 15, ty = tid >> 4;

    float acc[8][8];
#pragma unroll
    for (int i = 0; i < 8; i++)
#pragma unroll
        for (int j = 0; j < 8; j++) acc[i][j] = 0.f;

    const int arow = tid >> 1;          // 0..127
    const int acol = (tid & 1) * 4;     // 0 or 4
    const int brw  = tid >> 5;          // 0..7
    const int bcl  = (tid & 31) * 4;    // 0..124

    const float* Aptr = A + (size_t)(brow + arow) * lda + acol;
    const float* Bptr = B + (size_t)brw * ldb + bcol + bcl;
    const bool bok = (bcol + bcl) < N;

    for (int k0 = 0; k0 < K; k0 += 8) {
        float4 a = *(const float4*)(Aptr + k0);
        As[acol + 0][arow] = a.x;
        As[acol + 1][arow] = a.y;
        As[acol + 2][arow] = a.z;
        As[acol + 3][arow] = a.w;
        float4 b = bok ? *(const float4*)(Bptr + (size_t)k0 * ldb)
                       : make_float4(0.f, 0.f, 0.f, 0.f);
        *(float4*)&Bs[brw][bcl] = b;
        __syncthreads();
#pragma unroll
        for (int k = 0; k < 8; k++) {
            float ar[8], br[8];
            *(float4*)&ar[0] = *(const float4*)&As[k][ty * 8];
            *(float4*)&ar[4] = *(const float4*)&As[k][ty * 8 + 4];
            *(float4*)&br[0] = *(const float4*)&Bs[k][tx * 8];
            *(float4*)&br[4] = *(const float4*)&Bs[k][tx * 8 + 4];
#pragma unroll
            for (int i = 0; i < 8; i++)
#pragma unroll
                for (int j = 0; j < 8; j++)
                    acc[i][j] = fmaf(ar[i], br[j], acc[i][j]);
        }
        __syncthreads();
    }

#pragma unroll
    for (int i = 0; i < 8; i++) {
        const int row = brow + ty * 8 + i;
#pragma unroll
        for (int j4 = 0; j4 < 8; j4 += 4) {
            const int col = bcol + tx * 8 + j4;
            if (col < N)
                *(float4*)&C[(size_t)row * ldc + col] =
                    make_float4(acc[i][j4], acc[i][j4 + 1], acc[i][j4 + 2], acc[i][j4 + 3]);
        }
    }
}

// ---------------- RMSNorm in place (first `width` cols of a `stride` row) --
__global__ void rmsnorm_kernel(float* __restrict__ x, const float* __restrict__ g,
                               int width, int stride) {
    const int row = blockIdx.x;
    float* p = x + (size_t)row * stride;
    const int tid = threadIdx.x;
    float s = 0.f;
    for (int i = tid; i < width; i += 256) {
        float v = p[i];
        s += v * v;
    }
    __shared__ float red[256];
    red[tid] = s;
    __syncthreads();
    for (int o = 128; o > 0; o >>= 1) {
        if (tid < o) red[tid] += red[tid + o];
        __syncthreads();
    }
    const float inv = rsqrtf(red[0] / (float)width + 1e-6f);
    for (int i = tid; i < width; i += 256) p[i] = p[i] * inv * g[i];
}

// ---------------- RoPE (GPT-J interleaved pairing, per-element angle) ------
// out[i] = x[i]*cos(a_i) + rot[i]*sin(a_i); rot[2p]=-x[2p+1], rot[2p+1]=x[2p]
// a_i = pos * theta^(-(i mod 32)/32); pair partner i^1 is in the same warp,
// so exchange via shfl (no smem, no sync, no in-place race).
__device__ __forceinline__ float rope_angle(float fpos, int i) {
    return fpos * powf(10000.0f, -(float)(i & 31) * (1.0f / 32.0f));
}

__global__ void rope_q_kernel(float* __restrict__ q, const int* __restrict__ pos) {
    const int t = blockIdx.x, h = blockIdx.y, i = threadIdx.x;  // i in [0,64)
    float* p = q + (size_t)t * QW + h * QDIM + DQ;
    const float x = p[i];
    const float xp = __shfl_xor_sync(0xffffffffu, x, 1);
    float sn, cs;
    sincosf(rope_angle((float)pos[t], i), &sn, &cs);
    const float rot = (i & 1) ? xp : -xp;
    p[i] = x * cs + rot * sn;
}

__global__ void rope_k_kernel(const float* __restrict__ kvbuf, float* __restrict__ kpe,
                              const int* __restrict__ pos) {
    const int t = blockIdx.x, i = threadIdx.x;  // i in [0,64)
    const float* p = kvbuf + (size_t)t * KV_W + KVLORA;
    const float x = p[i];
    const float xp = __shfl_xor_sync(0xffffffffu, x, 1);
    float sn, cs;
    sincosf(rope_angle((float)pos[t], i), &sn, &cs);
    const float rot = (i & 1) ? xp : -xp;
    kpe[(size_t)t * DR + i] = x * cs + rot * sn;
}

// ---------------- flash attention (fp32, causal, online softmax) -----------
// grid: (32 q-blocks, 32 heads), 256 threads (tx 0..15, ty 0..15)
// tiles: 64 q rows x 64 k cols; thread owns rows ty*4+{0..3}, cols tx+16*{0..3}
// output: thread owns rows ty*4+{0..3}, dv cols tx+16*{0..7}
#define QSTR 193
#define KSTR 193
#define VSTR 128
#define PSTR 65
#define FLASH_SMEM ((64 * QSTR + 64 * KSTR + 64 * VSTR + 64 * PSTR) * 4)

__global__ void flash_kernel(const float* __restrict__ q,
                             const float* __restrict__ kvup,
                             const float* __restrict__ kpe,
                             float* __restrict__ out) {
    const int ib = blockIdx.x;
    const int h = blockIdx.y;
    const int tid = threadIdx.x;
    const int tx = tid & 15, ty = tid >> 4;

    extern __shared__ float sm[];
    float* sQ = sm;                    // 64 x 193
    float* sK = sQ + 64 * QSTR;        // 64 x 193
    float* sV = sK + 64 * KSTR;        // 64 x 128
    float* sP = sV + 64 * VSTR;        // 64 x 65

    const float scale = 0.07216878364870323f;  // (DQ+DR)^-0.5

    for (int idx = tid; idx < 64 * 192; idx += 256) {
        const int r = idx / 192, d = idx - r * 192;
        sQ[r * QSTR + d] = q[(size_t)(ib * 64 + r) * QW + h * QDIM + d] * scale;
    }

    float m[4], l[4], O[4][8];
#pragma unroll
    for (int i = 0; i < 4; i++) {
        m[i] = -INFINITY;
        l[i] = 0.f;
#pragma unroll
        for (int j = 0; j < 8; j++) O[i][j] = 0.f;
    }

    for (int jb = 0; jb <= ib; jb++) {
        __syncthreads();  // prior iteration done with sK/sV/sP (and sQ load done)
        for (int idx = tid; idx < 64 * 192; idx += 256) {
            const int r = idx / 192, d = idx - r * 192;
            const int kt = jb * 64 + r;
            sK[r * KSTR + d] = (d < DQ) ? kvup[(size_t)kt * KVUPW + h * (DQ + DV) + d]
                                        : kpe[(size_t)kt * DR + (d - DQ)];
        }
        for (int idx = tid; idx < 64 * 128; idx += 256) {
            const int r = idx >> 7, d = idx & 127;
            sV[r * VSTR + d] = kvup[(size_t)(jb * 64 + r) * KVUPW + h * (DQ + DV) + DQ + d];
        }
        __syncthreads();

        float S[4][4];
#pragma unroll
        for (int i = 0; i < 4; i++)
#pragma unroll
            for (int j = 0; j < 4; j++) S[i][j] = 0.f;

        for (int d = 0; d < 192; d++) {
            float qv[4], kv[4];
#pragma unroll
            for (int i = 0; i < 4; i++) qv[i] = sQ[(ty * 4 + i) * QSTR + d];
#pragma unroll
            for (int j = 0; j < 4; j++) kv[j] = sK[(tx + 16 * j) * KSTR + d];
#pragma unroll
            for (int i = 0; i < 4; i++)
#pragma unroll
                for (int j = 0; j < 4; j++) S[i][j] = fmaf(qv[i], kv[j], S[i][j]);
        }

        if (jb == ib) {
#pragma unroll
            for (int i = 0; i < 4; i++)
#pragma unroll
                for (int j = 0; j < 4; j++)
                    if (tx + 16 * j > ty * 4 + i) S[i][j] = -1e30f;
        }

#pragma unroll
        for (int i = 0; i < 4; i++) {
            float rmax = S[i][0];
#pragma unroll
            for (int j = 1; j < 4; j++) rmax = fmaxf(rmax, S[i][j]);
#pragma unroll
            for (int off = 1; off < 16; off <<= 1)
                rmax = fmaxf(rmax, __shfl_xor_sync(0xffffffffu, rmax, off));
            const float mn = fmaxf(m[i], rmax);
            const float alpha = __expf(m[i] - mn);
            m[i] = mn;
            float P[4];
            float rs = 0.f;
#pragma unroll
            for (int j = 0; j < 4; j++) {
                P[j] = __expf(S[i][j] - mn);
                rs += P[j];
            }
#pragma unroll
            for (int off = 1; off < 16; off <<= 1)
                rs += __shfl_xor_sync(0xffffffffu, rs, off);
            l[i] = l[i] * alpha + rs;
#pragma unroll
            for (int c = 0; c < 8; c++) O[i][c] *= alpha;
#pragma unroll
            for (int j = 0; j < 4; j++) sP[(ty * 4 + i) * PSTR + tx + 16 * j] = P[j];
        }
        __syncthreads();

        for (int k = 0; k < 64; k++) {
            float pv[4], vv[8];
#pragma unroll
            for (int i = 0; i < 4; i++) pv[i] = sP[(ty * 4 + i) * PSTR + k];
#pragma unroll
            for (int c = 0; c < 8; c++) vv[c] = sV[k * VSTR + tx + 16 * c];
#pragma unroll
            for (int i = 0; i < 4; i++)
#pragma unroll
                for (int c = 0; c < 8; c++) O[i][c] = fmaf(pv[i], vv[c], O[i][c]);
        }
    }

#pragma unroll
    for (int i = 0; i < 4; i++) {
        const float inv = 1.f / l[i];
        const int t = ib * 64 + ty * 4 + i;
#pragma unroll
        for (int c = 0; c < 8; c++)
            out[(size_t)t * ATTNW + h * DV + tx + 16 * c] = O[i][c] * inv;
    }
}

// ---------------- launch -----------------------------------------------------
extern "C" void kernel_launch(void* const* d_in, const int* in_sizes, int n_in,
                              void* d_out, int out_size) {
    const int* positions = (const int*)d_in[0];
    const float* hidden = (const float*)d_in[1];
    const float* w_qa = (const float*)d_in[2];
    const float* gamma_q = (const float*)d_in[3];
    const float* w_qb = (const float*)d_in[4];
    const float* w_kva = (const float*)d_in[5];
    const float* gamma_kv = (const float*)d_in[6];
    const float* w_kvb = (const float*)d_in[7];
    const float* w_o = (const float*)d_in[8];
    float* out = (float*)d_out;

    float *qa, *kv, *q, *kvup, *kpe, *attn;
    cudaGetSymbolAddress((void**)&qa, g_qa);
    cudaGetSymbolAddress((void**)&kv, g_kv);
    cudaGetSymbolAddress((void**)&q, g_q);
    cudaGetSymbolAddress((void**)&kvup, g_kvup);
    cudaGetSymbolAddress((void**)&kpe, g_kpe);
    cudaGetSymbolAddress((void**)&attn, g_attn);

    const int MB = T_TOK / 128;  // 16

    // q_a = hidden @ w_qa            [2048,1536]
    sgemm_kernel<<<dim3(QLORA / 128, MB), 256>>>(hidden, HIDDEN, w_qa, QLORA, qa, QLORA,
                                                 T_TOK, QLORA, HIDDEN);
    // kv = hidden @ w_kva            [2048,576]
    sgemm_kernel<<<dim3((KV_W + 127) / 128, MB), 256>>>(hidden, HIDDEN, w_kva, KV_W, kv, KV_W,
                                                        T_TOK, KV_W, HIDDEN);
    // rmsnorm
    rmsnorm_kernel<<<T_TOK, 256>>>(qa, gamma_q, QLORA, QLORA);
    rmsnorm_kernel<<<T_TOK, 256>>>(kv, gamma_kv, KVLORA, KV_W);
    // q = q_c @ w_qb                 [2048,6144]
    sgemm_kernel<<<dim3(QW / 128, MB), 256>>>(qa, QLORA, w_qb, QW, q, QW,
                                              T_TOK, QW, QLORA);
    // kv_up = kv_c @ w_kvb           [2048,8192]  (A stride 576, K=512)
    sgemm_kernel<<<dim3(KVUPW / 128, MB), 256>>>(kv, KV_W, w_kvb, KVUPW, kvup, KVUPW,
                                                 T_TOK, KVUPW, KVLORA);
    // RoPE
    rope_q_kernel<<<dim3(T_TOK, NH), 64>>>(q, positions);
    rope_k_kernel<<<T_TOK, 64>>>(kv, kpe, positions);
    // attention
    cudaFuncSetAttribute(flash_kernel, cudaFuncAttributeMaxDynamicSharedMemorySize, FLASH_SMEM);
    flash_kernel<<<dim3(T_TOK / 64, NH), 256, FLASH_SMEM>>>(q, kvup, kpe, attn);
    // out = attn @ w_o               [2048,5120]
    sgemm_kernel<<<dim3(HIDDEN / 128, MB), 256>>>(attn, ATTNW, w_o, HIDDEN, out, HIDDEN,
                                                  T_TOK, HIDDEN, ATTNW);
}

// round 5
// speedup vs baseline: 1.9861x; 1.9861x over previous
#include <cuda_runtime.h>
#include <math.h>
#include <stdint.h>

#define T_TOK 2048
#define HIDDEN 5120
#define NH 32
#define DQ 128
#define DR 64
#define DV 128
#define QLORA 1536
#define KVLORA 512
#define KV_W (KVLORA + DR)        // 576
#define QDIM (DQ + DR)            // 192
#define KVUPW (NH * (DQ + DV))    // 8192
#define QW (NH * QDIM)            // 6144
#define ATTNW (NH * DV)           // 4096

// ---------------- scratch (device globals; no runtime allocation) ----------
__device__ float g_qa[T_TOK * QLORA];
__device__ float g_kv[T_TOK * KV_W];
__device__ float g_q[T_TOK * QW];
__device__ float g_kvup[T_TOK * KVUPW];
__device__ float g_kpe[T_TOK * DR];
__device__ float g_attn[T_TOK * ATTNW];

// ======================= helpers ===========================================
__device__ __forceinline__ uint32_t smem_u32(const void* p) {
    uint32_t a;
    asm("{ .reg .u64 t; cvta.to.shared.u64 t, %1; cvt.u32.u64 %0, t; }"
        : "=r"(a) : "l"(p));
    return a;
}

__device__ __forceinline__ uint32_t f2tf32(float x) {
    uint32_t u;
    asm("cvt.rna.tf32.f32 %0, %1;" : "=r"(u) : "f"(x));
    return u;
}

__device__ __forceinline__ void mma_tf32(float c[4], const uint32_t a[4],
                                         const uint32_t b[2]) {
    asm volatile(
        "mma.sync.aligned.m16n8k8.row.col.f32.tf32.tf32.f32 "
        "{%0,%1,%2,%3}, {%4,%5,%6,%7}, {%8,%9}, {%0,%1,%2,%3};"
        : "+f"(c[0]), "+f"(c[1]), "+f"(c[2]), "+f"(c[3])
        : "r"(a[0]), "r"(a[1]), "r"(a[2]), "r"(a[3]), "r"(b[0]), "r"(b[1]));
}

// ======================= tf32 mma.sync GEMM ================================
// C[M,N] = A[M,K] @ B[K,N]; M mult of 128, K mult of 32, N mult of 4.
// CTA 128x128, BK=32, 256 threads (8 warps: 4m x 2n; warp tile 32x64).
// smem: 2 stages x (A 128x32 f32 = 16KB, B 32x128 f32 = 16KB) = 64KB.
// A smem [row][k], 16B chunk swizzle: chunk ^= (row&7)
// B smem [k][n],   16B chunk swizzle: chunk ^= (k&3)<<1
#define GSTAGE 32768
#define GSMEM (2 * GSTAGE)

__device__ __forceinline__ void g_load_stage(uint32_t sbase, int s,
        const float* __restrict__ A, int lda,
        const float* __restrict__ B, int ldb,
        int brow, int bcol, int N, int k0, int tid) {
    const uint32_t sA = sbase + s * GSTAGE;
    const uint32_t sB = sA + 16384;
#pragma unroll
    for (int it = 0; it < 4; it++) {
        const int f4 = it * 256 + tid;
        const int r = f4 >> 3, c16 = f4 & 7;
        const uint32_t dst = sA + r * 128 + ((c16 ^ (r & 7)) << 4);
        const float* src = A + (size_t)(brow + r) * lda + k0 + c16 * 4;
        asm volatile("cp.async.ca.shared.global [%0], [%1], 16;"
                     :: "r"(dst), "l"(src) : "memory");
    }
#pragma unroll
    for (int it = 0; it < 4; it++) {
        const int f4 = it * 256 + tid;
        const int k = f4 >> 5, c16 = f4 & 31;
        const uint32_t dst = sB + k * 512 + ((c16 ^ ((k & 3) << 1)) << 4);
        const float* src = B + (size_t)(k0 + k) * ldb + bcol + c16 * 4;
        const int sz = (bcol + c16 * 4 + 4 <= N) ? 16 : 0;
        asm volatile("cp.async.ca.shared.global [%0], [%1], 16, %2;"
                     :: "r"(dst), "l"(src), "r"(sz) : "memory");
    }
    asm volatile("cp.async.commit_group;" ::: "memory");
}

__global__ __launch_bounds__(256, 2) void sgemm_mma(
        const float* __restrict__ A, int lda,
        const float* __restrict__ B, int ldb,
        float* __restrict__ C, int ldc, int N, int K) {
    extern __shared__ char sm[];
    const uint32_t sbase = smem_u32(sm);
    const int tid = threadIdx.x;
    const int lane = tid & 31;
    const int wid = tid >> 5;
    const int wm = wid >> 1, wn = wid & 1;   // warp grid 4x2
    const int brow = blockIdx.y * 128;
    const int bcol = blockIdx.x * 128;

    float acc[2][8][4];
#pragma unroll
    for (int mi = 0; mi < 2; mi++)
#pragma unroll
        for (int ni = 0; ni < 8; ni++)
#pragma unroll
            for (int j = 0; j < 4; j++) acc[mi][ni][j] = 0.f;

    const int nch = K / 32;
    g_load_stage(sbase, 0, A, lda, B, ldb, brow, bcol, N, 0, tid);

    for (int i = 0; i < nch; i++) {
        const int s = i & 1;
        if (i + 1 < nch) {
            g_load_stage(sbase, s ^ 1, A, lda, B, ldb, brow, bcol, N,
                         (i + 1) * 32, tid);
            asm volatile("cp.async.wait_group 1;" ::: "memory");
        } else {
            asm volatile("cp.async.wait_group 0;" ::: "memory");
        }
        __syncthreads();

        const float* sA = (const float*)(sm + s * GSTAGE);
        const float* sB = (const float*)(sm + s * GSTAGE + 16384);

#pragma unroll
        for (int ks = 0; ks < 4; ks++) {
            uint32_t a[2][4];
            const int q = lane >> 2, rlo = lane & 3;
            const int c0 = ks * 8 + rlo;  // a cols c0, c0+4
#pragma unroll
            for (int mi = 0; mi < 2; mi++) {
                const int r0 = wm * 32 + mi * 16 + q;
                const int r1 = r0 + 8;
                a[mi][0] = f2tf32(sA[r0 * 32 + ((((c0 >> 2) ^ (r0 & 7))) << 2) + rlo]);
                a[mi][1] = f2tf32(sA[r1 * 32 + ((((c0 >> 2) ^ (r1 & 7))) << 2) + rlo]);
                a[mi][2] = f2tf32(sA[r0 * 32 + (((((c0 + 4) >> 2) ^ (r0 & 7))) << 2) + rlo]);
                a[mi][3] = f2tf32(sA[r1 * 32 + (((((c0 + 4) >> 2) ^ (r1 & 7))) << 2) + rlo]);
            }
            uint32_t b[8][2];
            const int kb0 = ks * 8 + rlo, kb1 = kb0 + 4;
#pragma unroll
            for (int ni = 0; ni < 8; ni++) {
                const int n = wn * 64 + ni * 8 + q;
                b[ni][0] = f2tf32(sB[kb0 * 128 + (((n >> 2) ^ ((kb0 & 3) << 1)) << 2) + (n & 3)]);
                b[ni][1] = f2tf32(sB[kb1 * 128 + (((n >> 2) ^ ((kb1 & 3) << 1)) << 2) + (n & 3)]);
            }
#pragma unroll
            for (int mi = 0; mi < 2; mi++)
#pragma unroll
                for (int ni = 0; ni < 8; ni++)
                    mma_tf32(acc[mi][ni], a[mi], b[ni]);
        }
        __syncthreads();
    }

    // epilogue: direct global stores (float2), cols guarded vs N
    const int q = lane >> 2, rlo = lane & 3;
#pragma unroll
    for (int mi = 0; mi < 2; mi++) {
        const int r0 = brow + wm * 32 + mi * 16 + q;
#pragma unroll
        for (int ni = 0; ni < 8; ni++) {
            const int col = bcol + wn * 64 + ni * 8 + rlo * 2;
            if (col < N) {
                *(float2*)&C[(size_t)r0 * ldc + col] =
                    make_float2(acc[mi][ni][0], acc[mi][ni][1]);
                *(float2*)&C[(size_t)(r0 + 8) * ldc + col] =
                    make_float2(acc[mi][ni][2], acc[mi][ni][3]);
            }
        }
    }
}

// ---------------- RMSNorm in place -----------------------------------------
__global__ void rmsnorm_kernel(float* __restrict__ x, const float* __restrict__ g,
                               int width, int stride) {
    const int row = blockIdx.x;
    float* p = x + (size_t)row * stride;
    const int tid = threadIdx.x;
    float s = 0.f;
    for (int i = tid; i < width; i += 256) {
        float v = p[i];
        s += v * v;
    }
    __shared__ float red[256];
    red[tid] = s;
    __syncthreads();
    for (int o = 128; o > 0; o >>= 1) {
        if (tid < o) red[tid] += red[tid + o];
        __syncthreads();
    }
    const float inv = rsqrtf(red[0] / (float)width + 1e-6f);
    for (int i = tid; i < width; i += 256) p[i] = p[i] * inv * g[i];
}

// ---------------- RoPE ------------------------------------------------------
__device__ __forceinline__ float rope_angle(float fpos, int i) {
    return fpos * powf(10000.0f, -(float)(i & 31) * (1.0f / 32.0f));
}

__global__ void rope_q_kernel(float* __restrict__ q, const int* __restrict__ pos) {
    const int t = blockIdx.x, h = blockIdx.y, i = threadIdx.x;  // i in [0,64)
    float* p = q + (size_t)t * QW + h * QDIM + DQ;
    const float x = p[i];
    const float xp = __shfl_xor_sync(0xffffffffu, x, 1);
    float sn, cs;
    sincosf(rope_angle((float)pos[t], i), &sn, &cs);
    const float rot = (i & 1) ? xp : -xp;
    p[i] = x * cs + rot * sn;
}

__global__ void rope_k_kernel(const float* __restrict__ kvbuf, float* __restrict__ kpe,
                              const int* __restrict__ pos) {
    const int t = blockIdx.x, i = threadIdx.x;  // i in [0,64)
    const float* p = kvbuf + (size_t)t * KV_W + KVLORA;
    const float x = p[i];
    const float xp = __shfl_xor_sync(0xffffffffu, x, 1);
    float sn, cs;
    sincosf(rope_angle((float)pos[t], i), &sn, &cs);
    const float rot = (i & 1) ? xp : -xp;
    kpe[(size_t)t * DR + i] = x * cs + rot * sn;
}

// ---------------- flash attention (fp32, causal, online softmax) -----------
#define QSTR 193
#define KSTR 193
#define VSTR 128
#define PSTR 65
#define FLASH_SMEM ((64 * QSTR + 64 * KSTR + 64 * VSTR + 64 * PSTR) * 4)

__global__ void flash_kernel(const float* __restrict__ q,
                             const float* __restrict__ kvup,
                             const float* __restrict__ kpe,
                             float* __restrict__ out) {
    const int ib = blockIdx.x;
    const int h = blockIdx.y;
    const int tid = threadIdx.x;
    const int tx = tid & 15, ty = tid >> 4;

    extern __shared__ float fsm[];
    float* sQ = fsm;
    float* sK = sQ + 64 * QSTR;
    float* sV = sK + 64 * KSTR;
    float* sP = sV + 64 * VSTR;

    const float scale = 0.07216878364870323f;  // (DQ+DR)^-0.5

    for (int idx = tid; idx < 64 * 192; idx += 256) {
        const int r = idx / 192, d = idx - r * 192;
        sQ[r * QSTR + d] = q[(size_t)(ib * 64 + r) * QW + h * QDIM + d] * scale;
    }

    float m[4], l[4], O[4][8];
#pragma unroll
    for (int i = 0; i < 4; i++) {
        m[i] = -INFINITY;
        l[i] = 0.f;
#pragma unroll
        for (int j = 0; j < 8; j++) O[i][j] = 0.f;
    }

    for (int jb = 0; jb <= ib; jb++) {
        __syncthreads();
        for (int idx = tid; idx < 64 * 192; idx += 256) {
            const int r = idx / 192, d = idx - r * 192;
            const int kt = jb * 64 + r;
            sK[r * KSTR + d] = (d < DQ) ? kvup[(size_t)kt * KVUPW + h * (DQ + DV) + d]
                                        : kpe[(size_t)kt * DR + (d - DQ)];
        }
        for (int idx = tid; idx < 64 * 128; idx += 256) {
            const int r = idx >> 7, d = idx & 127;
            sV[r * VSTR + d] = kvup[(size_t)(jb * 64 + r) * KVUPW + h * (DQ + DV) + DQ + d];
        }
        __syncthreads();

        float S[4][4];
#pragma unroll
        for (int i = 0; i < 4; i++)
#pragma unroll
            for (int j = 0; j < 4; j++) S[i][j] = 0.f;

        for (int d = 0; d < 192; d++) {
            float qv[4], kv[4];
#pragma unroll
            for (int i = 0; i < 4; i++) qv[i] = sQ[(ty * 4 + i) * QSTR + d];
#pragma unroll
            for (int j = 0; j < 4; j++) kv[j] = sK[(tx + 16 * j) * KSTR + d];
#pragma unroll
            for (int i = 0; i < 4; i++)
#pragma unroll
                for (int j = 0; j < 4; j++) S[i][j] = fmaf(qv[i], kv[j], S[i][j]);
        }

        if (jb == ib) {
#pragma unroll
            for (int i = 0; i < 4; i++)
#pragma unroll
                for (int j = 0; j < 4; j++)
                    if (tx + 16 * j > ty * 4 + i) S[i][j] = -1e30f;
        }

#pragma unroll
        for (int i = 0; i < 4; i++) {
            float rmax = S[i][0];
#pragma unroll
            for (int j = 1; j < 4; j++) rmax = fmaxf(rmax, S[i][j]);
#pragma unroll
            for (int off = 1; off < 16; off <<= 1)
                rmax = fmaxf(rmax, __shfl_xor_sync(0xffffffffu, rmax, off));
            const float mn = fmaxf(m[i], rmax);
            const float alpha = __expf(m[i] - mn);
            m[i] = mn;
            float P[4];
            float rs = 0.f;
#pragma unroll
            for (int j = 0; j < 4; j++) {
                P[j] = __expf(S[i][j] - mn);
                rs += P[j];
            }
#pragma unroll
            for (int off = 1; off < 16; off <<= 1)
                rs += __shfl_xor_sync(0xffffffffu, rs, off);
            l[i] = l[i] * alpha + rs;
#pragma unroll
            for (int c = 0; c < 8; c++) O[i][c] *= alpha;
#pragma unroll
            for (int j = 0; j < 4; j++) sP[(ty * 4 + i) * PSTR + tx + 16 * j] = P[j];
        }
        __syncthreads();

        for (int k = 0; k < 64; k++) {
            float pv[4], vv[8];
#pragma unroll
            for (int i = 0; i < 4; i++) pv[i] = sP[(ty * 4 + i) * PSTR + k];
#pragma unroll
            for (int c = 0; c < 8; c++) vv[c] = sV[k * VSTR + tx + 16 * c];
#pragma unroll
            for (int i = 0; i < 4; i++)
#pragma unroll
                for (int c = 0; c < 8; c++) O[i][c] = fmaf(pv[i], vv[c], O[i][c]);
        }
    }

#pragma unroll
    for (int i = 0; i < 4; i++) {
        const float inv = 1.f / l[i];
        const int t = ib * 64 + ty * 4 + i;
#pragma unroll
        for (int c = 0; c < 8; c++)
            out[(size_t)t * ATTNW + h * DV + tx + 16 * c] = O[i][c] * inv;
    }
}

// ---------------- launch -----------------------------------------------------
extern "C" void kernel_launch(void* const* d_in, const int* in_sizes, int n_in,
                              void* d_out, int out_size) {
    const int* positions = (const int*)d_in[0];
    const float* hidden = (const float*)d_in[1];
    const float* w_qa = (const float*)d_in[2];
    const float* gamma_q = (const float*)d_in[3];
    const float* w_qb = (const float*)d_in[4];
    const float* w_kva = (const float*)d_in[5];
    const float* gamma_kv = (const float*)d_in[6];
    const float* w_kvb = (const float*)d_in[7];
    const float* w_o = (const float*)d_in[8];
    float* out = (float*)d_out;

    float *qa, *kv, *q, *kvup, *kpe, *attn;
    cudaGetSymbolAddress((void**)&qa, g_qa);
    cudaGetSymbolAddress((void**)&kv, g_kv);
    cudaGetSymbolAddress((void**)&q, g_q);
    cudaGetSymbolAddress((void**)&kvup, g_kvup);
    cudaGetSymbolAddress((void**)&kpe, g_kpe);
    cudaGetSymbolAddress((void**)&attn, g_attn);

    cudaFuncSetAttribute(sgemm_mma, cudaFuncAttributeMaxDynamicSharedMemorySize, GSMEM);
    cudaFuncSetAttribute(flash_kernel, cudaFuncAttributeMaxDynamicSharedMemorySize,
                         FLASH_SMEM);

    const int MB = T_TOK / 128;  // 16

    // q_a = hidden @ w_qa            [2048,1536]
    sgemm_mma<<<dim3(QLORA / 128, MB), 256, GSMEM>>>(
        hidden, HIDDEN, w_qa, QLORA, qa, QLORA, QLORA, HIDDEN);
    // kv = hidden @ w_kva            [2048,576]
    sgemm_mma<<<dim3((KV_W + 127) / 128, MB), 256, GSMEM>>>(
        hidden, HIDDEN, w_kva, KV_W, kv, KV_W, KV_W, HIDDEN);
    // rmsnorm
    rmsnorm_kernel<<<T_TOK, 256>>>(qa, gamma_q, QLORA, QLORA);
    rmsnorm_kernel<<<T_TOK, 256>>>(kv, gamma_kv, KVLORA, KV_W);
    // q = q_c @ w_qb                 [2048,6144]
    sgemm_mma<<<dim3(QW / 128, MB), 256, GSMEM>>>(
        qa, QLORA, w_qb, QW, q, QW, QW, QLORA);
    // kv_up = kv_c @ w_kvb           [2048,8192]
    sgemm_mma<<<dim3(KVUPW / 128, MB), 256, GSMEM>>>(
        kv, KV_W, w_kvb, KVUPW, kvup, KVUPW, KVUPW, KVLORA);
    // RoPE
    rope_q_kernel<<<dim3(T_TOK, NH), 64>>>(q, positions);
    rope_k_kernel<<<T_TOK, 64>>>(kv, kpe, positions);
    // attention
    flash_kernel<<<dim3(T_TOK / 64, NH), 256, FLASH_SMEM>>>(q, kvup, kpe, attn);
    // out = attn @ w_o               [2048,5120]
    sgemm_mma<<<dim3(HIDDEN / 128, MB), 256, GSMEM>>>(
        attn, ATTNW, w_o, HIDDEN, out, HIDDEN, HIDDEN, ATTNW);
}

// round 7
// speedup vs baseline: 4.1587x; 2.0939x over previous
#include <cuda_runtime.h>
#include <math.h>
#include <stdint.h>

#define T_TOK 2048
#define HIDDEN 5120
#define NH 32
#define DQ 128
#define DR 64
#define DV 128
#define QLORA 1536
#define KVLORA 512
#define KV_W (KVLORA + DR)        // 576
#define QDIM (DQ + DR)            // 192
#define KVUPW (NH * (DQ + DV))    // 8192
#define QW (NH * QDIM)            // 6144
#define ATTNW (NH * DV)           // 4096

// ---------------- scratch (device globals; no runtime allocation) ----------
__device__ float g_qa[T_TOK * QLORA];
__device__ float g_kv[T_TOK * KV_W];
__device__ float g_q[T_TOK * QW];
__device__ float g_kvup[T_TOK * KVUPW];
__device__ float g_kpe[T_TOK * DR];
__device__ float g_attn[T_TOK * ATTNW];
// tf32-pre-rounded copies of inputs
__device__ float g_hid_t[T_TOK * HIDDEN];
__device__ float g_wqa_t[HIDDEN * QLORA];
__device__ float g_wqb_t[QLORA * QW];
__device__ float g_wkva_t[HIDDEN * KV_W];
__device__ float g_wkvb_t[KVLORA * KVUPW];
__device__ float g_wo_t[ATTNW * HIDDEN];

// ======================= helpers ===========================================
__device__ __forceinline__ uint32_t smem_u32(const void* p) {
    uint32_t a;
    asm("{ .reg .u64 t; cvta.to.shared.u64 t, %1; cvt.u32.u64 %0, t; }"
        : "=r"(a) : "l"(p));
    return a;
}

__device__ __forceinline__ float tf32r(float x) {
    uint32_t u;
    asm("cvt.rna.tf32.f32 %0, %1;" : "=r"(u) : "f"(x));
    return __uint_as_float(u);
}

__device__ __forceinline__ void mma_tf32(float c[4], const uint32_t a[4],
                                         uint32_t b0, uint32_t b1) {
    asm volatile(
        "mma.sync.aligned.m16n8k8.row.col.f32.tf32.tf32.f32 "
        "{%0,%1,%2,%3}, {%4,%5,%6,%7}, {%8,%9}, {%0,%1,%2,%3};"
        : "+f"(c[0]), "+f"(c[1]), "+f"(c[2]), "+f"(c[3])
        : "r"(a[0]), "r"(a[1]), "r"(a[2]), "r"(a[3]), "r"(b0), "r"(b1));
}

// ---------------- tf32 pre-round pass --------------------------------------
__global__ void round_tf32_kernel(const float* __restrict__ in,
                                  float* __restrict__ o, int n4) {
    for (int i = blockIdx.x * 256 + threadIdx.x; i < n4; i += gridDim.x * 256) {
        float4 v = ((const float4*)in)[i];
        v.x = tf32r(v.x); v.y = tf32r(v.y); v.z = tf32r(v.z); v.w = tf32r(v.w);
        ((float4*)o)[i] = v;
    }
}

// ======================= tf32 mma.sync GEMM ================================
// C[M,N] = A[M,K] @ B[K,N]; operands PRE-ROUNDED to tf32 in gmem.
// M mult of 128, K mult of 32. CTA 128x128, BK=32, 256 threads (8 warps 4x2).
#define GSTAGE 32768
#define GSMEM (2 * GSTAGE)

__device__ __forceinline__ void g_load_stage(uint32_t sbase, int s,
        const float* __restrict__ A, int lda,
        const float* __restrict__ B, int ldb,
        int brow, int bcol, int N, int k0, int tid) {
    const uint32_t sA = sbase + s * GSTAGE;
    const uint32_t sB = sA + 16384;
#pragma unroll
    for (int it = 0; it < 4; it++) {
        const int f4 = it * 256 + tid;
        const int r = f4 >> 3, c16 = f4 & 7;
        const uint32_t dst = sA + r * 128 + ((c16 ^ (r & 7)) << 4);
        const float* src = A + (size_t)(brow + r) * lda + k0 + c16 * 4;
        asm volatile("cp.async.ca.shared.global [%0], [%1], 16;"
                     :: "r"(dst), "l"(src) : "memory");
    }
#pragma unroll
    for (int it = 0; it < 4; it++) {
        const int f4 = it * 256 + tid;
        const int k = f4 >> 5, c16 = f4 & 31;
        const uint32_t dst = sB + k * 512 + ((c16 ^ ((k & 3) << 1)) << 4);
        const float* src = B + (size_t)(k0 + k) * ldb + bcol + c16 * 4;
        const int sz = (bcol + c16 * 4 + 4 <= N) ? 16 : 0;
        asm volatile("cp.async.ca.shared.global [%0], [%1], 16, %2;"
                     :: "r"(dst), "l"(src), "r"(sz) : "memory");
    }
    asm volatile("cp.async.commit_group;" ::: "memory");
}

__global__ __launch_bounds__(256, 2) void sgemm_mma(
        const float* __restrict__ A, int lda,
        const float* __restrict__ B, int ldb,
        float* __restrict__ C, int ldc, int N, int K,
        float oscale, int rnd) {
    extern __shared__ char sm[];
    const uint32_t sbase = smem_u32(sm);
    const int tid = threadIdx.x;
    const int lane = tid & 31;
    const int wid = tid >> 5;
    const int wm = wid >> 1, wn = wid & 1;
    const int brow = blockIdx.y * 128;
    const int bcol = blockIdx.x * 128;

    float acc[2][8][4];
#pragma unroll
    for (int mi = 0; mi < 2; mi++)
#pragma unroll
        for (int ni = 0; ni < 8; ni++)
#pragma unroll
            for (int j = 0; j < 4; j++) acc[mi][ni][j] = 0.f;

    const int nch = K / 32;
    g_load_stage(sbase, 0, A, lda, B, ldb, brow, bcol, N, 0, tid);

    for (int i = 0; i < nch; i++) {
        const int s = i & 1;
        if (i + 1 < nch) {
            g_load_stage(sbase, s ^ 1, A, lda, B, ldb, brow, bcol, N,
                         (i + 1) * 32, tid);
            asm volatile("cp.async.wait_group 1;" ::: "memory");
        } else {
            asm volatile("cp.async.wait_group 0;" ::: "memory");
        }
        __syncthreads();

        const float* sA = (const float*)(sm + s * GSTAGE);
        const float* sB = (const float*)(sm + s * GSTAGE + 16384);

#pragma unroll
        for (int ks = 0; ks < 4; ks++) {
            uint32_t a[2][4];
            const int q = lane >> 2, rlo = lane & 3;
            const int c0 = ks * 8 + rlo;
#pragma unroll
            for (int mi = 0; mi < 2; mi++) {
                const int r0 = wm * 32 + mi * 16 + q;
                const int r1 = r0 + 8;
                a[mi][0] = __float_as_uint(sA[r0 * 32 + ((((c0 >> 2) ^ (r0 & 7))) << 2) + rlo]);
                a[mi][1] = __float_as_uint(sA[r1 * 32 + ((((c0 >> 2) ^ (r1 & 7))) << 2) + rlo]);
                a[mi][2] = __float_as_uint(sA[r0 * 32 + (((((c0 + 4) >> 2) ^ (r0 & 7))) << 2) + rlo]);
                a[mi][3] = __float_as_uint(sA[r1 * 32 + (((((c0 + 4) >> 2) ^ (r1 & 7))) << 2) + rlo]);
            }
            uint32_t b[8][2];
            const int kb0 = ks * 8 + rlo, kb1 = kb0 + 4;
#pragma unroll
            for (int ni = 0; ni < 8; ni++) {
                const int n = wn * 64 + ni * 8 + q;
                b[ni][0] = __float_as_uint(sB[kb0 * 128 + (((n >> 2) ^ ((kb0 & 3) << 1)) << 2) + (n & 3)]);
                b[ni][1] = __float_as_uint(sB[kb1 * 128 + (((n >> 2) ^ ((kb1 & 3) << 1)) << 2) + (n & 3)]);
            }
#pragma unroll
            for (int mi = 0; mi < 2; mi++)
#pragma unroll
                for (int ni = 0; ni < 8; ni++)
                    mma_tf32(acc[mi][ni], a[mi], b[ni][0], b[ni][1]);
        }
        __syncthreads();
    }

    const int q = lane >> 2, rlo = lane & 3;
#pragma unroll
    for (int mi = 0; mi < 2; mi++) {
        const int r0 = brow + wm * 32 + mi * 16 + q;
#pragma unroll
        for (int ni = 0; ni < 8; ni++) {
            const int col = bcol + wn * 64 + ni * 8 + rlo * 2;
            if (col < N) {
                float x0 = acc[mi][ni][0] * oscale, x1 = acc[mi][ni][1] * oscale;
                float x2 = acc[mi][ni][2] * oscale, x3 = acc[mi][ni][3] * oscale;
                if (rnd) {
                    x0 = tf32r(x0); x1 = tf32r(x1); x2 = tf32r(x2); x3 = tf32r(x3);
                }
                *(float2*)&C[(size_t)r0 * ldc + col] = make_float2(x0, x1);
                *(float2*)&C[(size_t)(r0 + 8) * ldc + col] = make_float2(x2, x3);
            }
        }
    }
}

// ---------------- RMSNorm in place (writes tf32-rounded) --------------------
__global__ void rmsnorm_kernel(float* __restrict__ x, const float* __restrict__ g,
                               int width, int stride) {
    const int row = blockIdx.x;
    float* p = x + (size_t)row * stride;
    const int tid = threadIdx.x;
    float s = 0.f;
    for (int i = tid; i < width; i += 256) {
        float v = p[i];
        s += v * v;
    }
    __shared__ float red[256];
    red[tid] = s;
    __syncthreads();
    for (int o = 128; o > 0; o >>= 1) {
        if (tid < o) red[tid] += red[tid + o];
        __syncthreads();
    }
    const float inv = rsqrtf(red[0] / (float)width + 1e-6f);
    for (int i = tid; i < width; i += 256) p[i] = tf32r(p[i] * inv * g[i]);
}

// ---------------- RoPE (writes tf32-rounded) --------------------------------
__device__ __forceinline__ float rope_angle(float fpos, int i) {
    return fpos * powf(10000.0f, -(float)(i & 31) * (1.0f / 32.0f));
}

__global__ void rope_q_kernel(float* __restrict__ q, const int* __restrict__ pos) {
    const int t = blockIdx.x, h = blockIdx.y, i = threadIdx.x;  // [0,64)
    float* p = q + (size_t)t * QW + h * QDIM + DQ;
    const float x = p[i];
    const float xp = __shfl_xor_sync(0xffffffffu, x, 1);
    float sn, cs;
    sincosf(rope_angle((float)pos[t], i), &sn, &cs);
    const float rot = (i & 1) ? xp : -xp;
    p[i] = tf32r(x * cs + rot * sn);
}

__global__ void rope_k_kernel(const float* __restrict__ kvbuf, float* __restrict__ kpe,
                              const int* __restrict__ pos) {
    const int t = blockIdx.x, i = threadIdx.x;  // [0,64)
    const float* p = kvbuf + (size_t)t * KV_W + KVLORA;
    const float x = p[i];
    const float xp = __shfl_xor_sync(0xffffffffu, x, 1);
    float sn, cs;
    sincosf(rope_angle((float)pos[t], i), &sn, &cs);
    const float rot = (i & 1) ? xp : -xp;
    kpe[(size_t)t * DR + i] = tf32r(x * cs + rot * sn);
}

// ================ flash attention, tf32 mma (causal, online softmax) =======
// grid (16, 32): 128 q rows per CTA, 8 warps (16 rows each), k-tiles of 64.
// All inputs pre-rounded tf32 (Q also pre-scaled by (DQ+DR)^-0.5).
#define FQP 196   // ≡4 (mod 32) banks, mult of 4 for float4
#define FKP 196
#define FVP 136   // ≡8 (mod 32)
#define FPP 72    // ≡8 (mod 32)
#define FLASH_SMEM ((128 * FQP + 64 * FKP + 64 * FVP + 128 * FPP) * 4)  // 222208

__global__ __launch_bounds__(256, 1) void flash_tc(
        const float* __restrict__ q, const float* __restrict__ kvup,
        const float* __restrict__ kpe, float* __restrict__ out) {
    const int ib = blockIdx.x;
    const int h = blockIdx.y;
    const int tid = threadIdx.x;
    const int lane = tid & 31;
    const int wid = tid >> 5;

    extern __shared__ float fs[];
    float* sQ = fs;
    float* sK = sQ + 128 * FQP;
    float* sV = sK + 64 * FKP;
    float* sP = sV + 64 * FVP;

    // Q tile: 128 rows x 192 (raw copy; already tf32+scaled)
    for (int idx = tid; idx < 128 * 48; idx += 256) {
        const int r = idx / 48, d4 = idx % 48;
        *(float4*)&sQ[r * FQP + d4 * 4] =
            *(const float4*)&q[(size_t)(ib * 128 + r) * QW + h * QDIM + d4 * 4];
    }

    const int r = lane >> 2, c2 = lane & 3;
    const int qr0 = ib * 128 + wid * 16 + r;   // rows qr0 and qr0+8
    float m0 = -INFINITY, m1 = -INFINITY, l0 = 0.f, l1 = 0.f;
    float O[16][4];
#pragma unroll
    for (int nt = 0; nt < 16; nt++)
#pragma unroll
        for (int j = 0; j < 4; j++) O[nt][j] = 0.f;

    const int njb = 2 * ib + 2;
    for (int jb = 0; jb < njb; jb++) {
        __syncthreads();
        // K tile: 64 tokens x 192 (nope | roped pe)
        for (int idx = tid; idx < 64 * 48; idx += 256) {
            const int rr = idx / 48, d4 = idx % 48;
            const int kt = jb * 64 + rr;
            float4 v;
            if (d4 < 32) v = *(const float4*)&kvup[(size_t)kt * KVUPW + h * 256 + d4 * 4];
            else         v = *(const float4*)&kpe[(size_t)kt * DR + (d4 - 32) * 4];
            *(float4*)&sK[rr * FKP + d4 * 4] = v;
        }
        // V tile: 64 x 128
        for (int idx = tid; idx < 64 * 32; idx += 256) {
            const int rr = idx >> 5, d4 = idx & 31;
            *(float4*)&sV[rr * FVP + d4 * 4] =
                *(const float4*)&kvup[(size_t)(jb * 64 + rr) * KVUPW + h * 256 + 128 + d4 * 4];
        }
        __syncthreads();

        // ---- S = Q K^T (tf32 mma) ----
        float S[8][4];
#pragma unroll
        for (int nt = 0; nt < 8; nt++)
#pragma unroll
            for (int j = 0; j < 4; j++) S[nt][j] = 0.f;

#pragma unroll
        for (int ks = 0; ks < 24; ks++) {
            uint32_t a[4];
            const int base = (wid * 16 + r) * FQP + ks * 8 + c2;
            a[0] = __float_as_uint(sQ[base]);
            a[1] = __float_as_uint(sQ[base + 8 * FQP]);
            a[2] = __float_as_uint(sQ[base + 4]);
            a[3] = __float_as_uint(sQ[base + 8 * FQP + 4]);
#pragma unroll
            for (int nt = 0; nt < 8; nt++) {
                const int kb = (nt * 8 + r) * FKP + ks * 8 + c2;
                mma_tf32(S[nt], a, __float_as_uint(sK[kb]),
                         __float_as_uint(sK[kb + 4]));
            }
        }

        // ---- causal mask (only last two tiles can violate) ----
        if (jb >= 2 * ib) {
#pragma unroll
            for (int nt = 0; nt < 8; nt++) {
                const int kc = jb * 64 + nt * 8 + c2 * 2;
                if (kc > qr0)     S[nt][0] = -1e30f;
                if (kc + 1 > qr0) S[nt][1] = -1e30f;
                if (kc > qr0 + 8)     S[nt][2] = -1e30f;
                if (kc + 1 > qr0 + 8) S[nt][3] = -1e30f;
            }
        }

        // ---- online softmax ----
        float mx0 = -INFINITY, mx1 = -INFINITY;
#pragma unroll
        for (int nt = 0; nt < 8; nt++) {
            mx0 = fmaxf(mx0, fmaxf(S[nt][0], S[nt][1]));
            mx1 = fmaxf(mx1, fmaxf(S[nt][2], S[nt][3]));
        }
        mx0 = fmaxf(mx0, __shfl_xor_sync(0xffffffffu, mx0, 1));
        mx0 = fmaxf(mx0, __shfl_xor_sync(0xffffffffu, mx0, 2));
        mx1 = fmaxf(mx1, __shfl_xor_sync(0xffffffffu, mx1, 1));
        mx1 = fmaxf(mx1, __shfl_xor_sync(0xffffffffu, mx1, 2));
        const float mn0 = fmaxf(m0, mx0), mn1 = fmaxf(m1, mx1);
        const float al0 = __expf(m0 - mn0), al1 = __expf(m1 - mn1);
        m0 = mn0; m1 = mn1;
        float rs0 = 0.f, rs1 = 0.f;
#pragma unroll
        for (int nt = 0; nt < 8; nt++) {
            const float p0 = __expf(S[nt][0] - mn0);
            const float p1 = __expf(S[nt][1] - mn0);
            const float p2 = __expf(S[nt][2] - mn1);
            const float p3 = __expf(S[nt][3] - mn1);
            rs0 += p0 + p1;
            rs1 += p2 + p3;
            const int pr = (wid * 16 + r) * FPP + nt * 8 + c2 * 2;
            *(float2*)&sP[pr] = make_float2(tf32r(p0), tf32r(p1));
            *(float2*)&sP[pr + 8 * FPP] = make_float2(tf32r(p2), tf32r(p3));
        }
        rs0 += __shfl_xor_sync(0xffffffffu, rs0, 1);
        rs0 += __shfl_xor_sync(0xffffffffu, rs0, 2);
        rs1 += __shfl_xor_sync(0xffffffffu, rs1, 1);
        rs1 += __shfl_xor_sync(0xffffffffu, rs1, 2);
        l0 = l0 * al0 + rs0;
        l1 = l1 * al1 + rs1;
#pragma unroll
        for (int nt = 0; nt < 16; nt++) {
            O[nt][0] *= al0; O[nt][1] *= al0;
            O[nt][2] *= al1; O[nt][3] *= al1;
        }
        __syncwarp();

        // ---- O += P V (tf32 mma) ----
#pragma unroll
        for (int kf = 0; kf < 8; kf++) {
            uint32_t a[4];
            const int pb = (wid * 16 + r) * FPP + kf * 8 + c2;
            a[0] = __float_as_uint(sP[pb]);
            a[1] = __float_as_uint(sP[pb + 8 * FPP]);
            a[2] = __float_as_uint(sP[pb + 4]);
            a[3] = __float_as_uint(sP[pb + 8 * FPP + 4]);
#pragma unroll
            for (int nt = 0; nt < 16; nt++) {
                const int vb = (kf * 8 + c2) * FVP + nt * 8 + r;
                mma_tf32(O[nt], a, __float_as_uint(sV[vb]),
                         __float_as_uint(sV[vb + 4 * FVP]));
            }
        }
    }

    // ---- epilogue: normalize + tf32-round (feeds w_o GEMM) ----
    const float inv0 = 1.f / l0, inv1 = 1.f / l1;
    const int row0 = ib * 128 + wid * 16 + r;
#pragma unroll
    for (int nt = 0; nt < 16; nt++) {
        const int col = h * DV + nt * 8 + c2 * 2;
        *(float2*)&out[(size_t)row0 * ATTNW + col] =
            make_float2(tf32r(O[nt][0] * inv0), tf32r(O[nt][1] * inv0));
        *(float2*)&out[(size_t)(row0 + 8) * ATTNW + col] =
            make_float2(tf32r(O[nt][2] * inv1), tf32r(O[nt][3] * inv1));
    }
}

// ---------------- launch -----------------------------------------------------
extern "C" void kernel_launch(void* const* d_in, const int* in_sizes, int n_in,
                              void* d_out, int out_size) {
    const int* positions = (const int*)d_in[0];
    const float* hidden = (const float*)d_in[1];
    const float* w_qa = (const float*)d_in[2];
    const float* gamma_q = (const float*)d_in[3];
    const float* w_qb = (const float*)d_in[4];
    const float* w_kva = (const float*)d_in[5];
    const float* gamma_kv = (const float*)d_in[6];
    const float* w_kvb = (const float*)d_in[7];
    const float* w_o = (const float*)d_in[8];
    float* out = (float*)d_out;

    float *qa, *kv, *q, *kvup, *kpe, *attn;
    float *hid_t, *wqa_t, *wqb_t, *wkva_t, *wkvb_t, *wo_t;
    cudaGetSymbolAddress((void**)&qa, g_qa);
    cudaGetSymbolAddress((void**)&kv, g_kv);
    cudaGetSymbolAddress((void**)&q, g_q);
    cudaGetSymbolAddress((void**)&kvup, g_kvup);
    cudaGetSymbolAddress((void**)&kpe, g_kpe);
    cudaGetSymbolAddress((void**)&attn, g_attn);
    cudaGetSymbolAddress((void**)&hid_t, g_hid_t);
    cudaGetSymbolAddress((void**)&wqa_t, g_wqa_t);
    cudaGetSymbolAddress((void**)&wqb_t, g_wqb_t);
    cudaGetSymbolAddress((void**)&wkva_t, g_wkva_t);
    cudaGetSymbolAddress((void**)&wkvb_t, g_wkvb_t);
    cudaGetSymbolAddress((void**)&wo_t, g_wo_t);

    cudaFuncSetAttribute(sgemm_mma, cudaFuncAttributeMaxDynamicSharedMemorySize, GSMEM);
    cudaFuncSetAttribute(flash_tc, cudaFuncAttributeMaxDynamicSharedMemorySize,
                         FLASH_SMEM);

    const float SCALE = 0.07216878364870323f;  // (DQ+DR)^-0.5
    const int MB = T_TOK / 128;  // 16

    // pre-round inputs to tf32
    round_tf32_kernel<<<2048, 256>>>(hidden, hid_t, T_TOK * HIDDEN / 4);
    round_tf32_kernel<<<2048, 256>>>(w_qa, wqa_t, HIDDEN * QLORA / 4);
    round_tf32_kernel<<<2048, 256>>>(w_qb, wqb_t, QLORA * QW / 4);
    round_tf32_kernel<<<2048, 256>>>(w_kva, wkva_t, HIDDEN * KV_W / 4);
    round_tf32_kernel<<<2048, 256>>>(w_kvb, wkvb_t, KVLORA * KVUPW / 4);
    round_tf32_kernel<<<2048, 256>>>(w_o, wo_t, ATTNW * HIDDEN / 4);

    // q_a = hidden @ w_qa            [2048,1536]
    sgemm_mma<<<dim3(QLORA / 128, MB), 256, GSMEM>>>(
        hid_t, HIDDEN, wqa_t, QLORA, qa, QLORA, QLORA, HIDDEN, 1.f, 0);
    // kv = hidden @ w_kva            [2048,576]
    sgemm_mma<<<dim3((KV_W + 127) / 128, MB), 256, GSMEM>>>(
        hid_t, HIDDEN, wkva_t, KV_W, kv, KV_W, KV_W, HIDDEN, 1.f, 0);
    // rmsnorm (writes tf32)
    rmsnorm_kernel<<<T_TOK, 256>>>(qa, gamma_q, QLORA, QLORA);
    rmsnorm_kernel<<<T_TOK, 256>>>(kv, gamma_kv, KVLORA, KV_W);
    // q = (q_c @ w_qb) * scale, tf32 [2048,6144]
    sgemm_mma<<<dim3(QW / 128, MB), 256, GSMEM>>>(
        qa, QLORA, wqb_t, QW, q, QW, QW, QLORA, SCALE, 1);
    // kv_up = kv_c @ w_kvb, tf32     [2048,8192]
    sgemm_mma<<<dim3(KVUPW / 128, MB), 256, GSMEM>>>(
        kv, KV_W, wkvb_t, KVUPW, kvup, KVUPW, KVUPW, KVLORA, 1.f, 1);
    // RoPE (writes tf32; q is pre-scaled, rotation commutes with scaling)
    rope_q_kernel<<<dim3(T_TOK, NH), 64>>>(q, positions);
    rope_k_kernel<<<T_TOK, 64>>>(kv, kpe, positions);
    // attention (tensor-core)
    flash_tc<<<dim3(T_TOK / 128, NH), 256, FLASH_SMEM>>>(q, kvup, kpe, attn);
    // out = attn @ w_o               [2048,5120]
    sgemm_mma<<<dim3(HIDDEN / 128, MB), 256, GSMEM>>>(
        attn, ATTNW, wo_t, HIDDEN, out, HIDDEN, HIDDEN, ATTNW, 1.f, 0);
}